// round 15
// baseline (speedup 1.0000x reference)
#include <cuda_runtime.h>
#include <cuda_fp16.h>
#include <cstdint>

#define M_TOK 65536   // B*N
#define C_DIM 1024
#define H_DIM 512
#define Q_DIM 256

// ----------------- device-global scratch ----------------------------------
__device__ float g_mu[M_TOK];
__device__ float g_rstd[M_TOK];
__device__ float g_bias2[H_DIM];
// LN'd input + intermediates, plain fp16, [m][k]
__device__ __half g_a0[(size_t)M_TOK * C_DIM];
__device__ __half g_h1[(size_t)M_TOK * H_DIM];
__device__ __half g_h2[(size_t)M_TOK * H_DIM];
__device__ float  g_h3[(size_t)M_TOK * Q_DIM];
// fp16 weights (single rounding), TRANSPOSED [n][k]
__device__ __half g_W1[H_DIM * C_DIM];
__device__ __half g_W2[H_DIM * H_DIM];
__device__ __half g_W3[Q_DIM * H_DIM];
__device__ int   g_fix_count;
__device__ int   g_fix_list[M_TOK];

// ----------------- helpers ------------------------------------------------
__device__ __forceinline__ float gelu_f(float v) {
    return 0.5f * v * (1.0f + erff(v * 0.70710678118654752440f));
}
__device__ __forceinline__ uint32_t pack2f(float a, float b) {
    __half2 h2 = __halves2half2(__float2half_rn(a), __float2half_rn(b));
    return *reinterpret_cast<uint32_t*>(&h2);
}
#define CPA16(dst, src) \
    asm volatile("cp.async.cg.shared.global [%0], [%1], 16;" :: "r"(dst), "l"(src) : "memory")
#define CPA_COMMIT() asm volatile("cp.async.commit_group;" ::: "memory")
#define CPA_WAIT0()  asm volatile("cp.async.wait_group 0;" ::: "memory")
#define CPA_WAIT1()  asm volatile("cp.async.wait_group 1;" ::: "memory")
__device__ __forceinline__ uint32_t smem_u32(const void* p) {
    uint32_t a;
    asm("{ .reg .u64 t; cvta.to.shared.u64 t, %1; cvt.u32.u64 %0, t; }" : "=r"(a) : "l"(p));
    return a;
}
__device__ __forceinline__ void ldsm4(uint32_t* r, uint32_t addr) {
    asm volatile("ldmatrix.sync.aligned.m8n8.x4.shared.b16 {%0,%1,%2,%3}, [%4];"
                 : "=r"(r[0]), "=r"(r[1]), "=r"(r[2]), "=r"(r[3]) : "r"(addr));
}
__device__ __forceinline__ void mma16(float* d, const uint32_t* a, uint32_t b0, uint32_t b1) {
    asm volatile(
        "mma.sync.aligned.m16n8k16.row.col.f32.f16.f16.f32 "
        "{%0,%1,%2,%3}, {%4,%5,%6,%7}, {%8,%9}, {%0,%1,%2,%3};"
        : "+f"(d[0]), "+f"(d[1]), "+f"(d[2]), "+f"(d[3])
        : "r"(a[0]), "r"(a[1]), "r"(a[2]), "r"(a[3]), "r"(b0), "r"(b1));
}

// ----------------- fused LN stats + apply + fp16 round ---------------------
__global__ __launch_bounds__(256)
void ln_apply_kernel(const float* __restrict__ x,
                     const float* __restrict__ lns, const float* __restrict__ lnb) {
    int row = (blockIdx.x * 256 + threadIdx.x) >> 5;
    int lane = threadIdx.x & 31;
    const float4* xr = (const float4*)(x + (size_t)row * C_DIM);
    float4 v[8];
    float s = 0.f, ss = 0.f;
#pragma unroll
    for (int i = 0; i < 8; ++i) {
        v[i] = xr[lane + 32 * i];
        s  += v[i].x + v[i].y + v[i].z + v[i].w;
        ss += v[i].x * v[i].x + v[i].y * v[i].y + v[i].z * v[i].z + v[i].w * v[i].w;
    }
#pragma unroll
    for (int o = 16; o; o >>= 1) {
        s  += __shfl_xor_sync(0xffffffffu, s, o);
        ss += __shfl_xor_sync(0xffffffffu, ss, o);
    }
    float mu = s * (1.0f / C_DIM);
    float var = ss * (1.0f / C_DIM) - mu * mu;
    float rs = rsqrtf(var + 1e-5f);
    if (lane == 0) { g_mu[row] = mu; g_rstd[row] = rs; }

    __half* dh = g_a0 + (size_t)row * C_DIM;
#pragma unroll
    for (int i = 0; i < 8; ++i) {
        int k = (lane + 32 * i) * 4;
        float4 sc = *(const float4*)(lns + k);
        float4 bi = *(const float4*)(lnb + k);
        float f0 = (v[i].x - mu) * rs * sc.x + bi.x;
        float f1 = (v[i].y - mu) * rs * sc.y + bi.y;
        float f2 = (v[i].z - mu) * rs * sc.z + bi.z;
        float f3 = (v[i].w - mu) * rs * sc.w + bi.w;
        *(uint2*)(dh + k) = make_uint2(pack2f(f0, f1), pack2f(f2, f3));
    }
}

// ----------------- weight prep: transpose + fp16 round ----------------------
__global__ void prep_w_kernel(const float* __restrict__ WL,
                              const float* __restrict__ Wl1,
                              const float* __restrict__ Wl2) {
    int i = blockIdx.x * blockDim.x + threadIdx.x;
    if (i == 0) g_fix_count = 0;
    const int S1 = H_DIM * C_DIM;
    const int S2 = S1 + H_DIM * H_DIM;
    const int S3 = S2 + Q_DIM * H_DIM;
    if (i < S1) {
        int n = i / C_DIM, k = i % C_DIM;
        g_W1[i] = __float2half_rn(WL[(size_t)k * H_DIM + n]);
    } else if (i < S2) {
        int j = i - S1;
        int n = j / H_DIM, k = j % H_DIM;          // Wl1 top half: rows 0..511
        g_W2[j] = __float2half_rn(Wl1[(size_t)k * H_DIM + n]);
    } else if (i < S3) {
        int j = i - S2;
        int n = j / H_DIM, k = j % H_DIM;
        g_W3[j] = __float2half_rn(Wl2[(size_t)k * Q_DIM + n]);
    }
}

// ----------------- bias2 = noise_feature @ W_l1[512:,:] (exact fp32) -------
__global__ void bias2_kernel(const float* __restrict__ nf,
                             const float* __restrict__ Wl1) {
    int j = blockIdx.x * blockDim.x + threadIdx.x;
    const float* wp = Wl1 + (size_t)H_DIM * H_DIM + j;
    float s = 0.f;
    for (int k = 0; k < H_DIM; ++k)
        s += nf[k] * wp[(size_t)k * H_DIM];
    g_bias2[j] = s;
}

// ----------------- fp16 GEMM, 3-stage cp.async pipeline --------------------
// per stage: A 128x80B (10240) | B 128x80B (10240) = 20480; 3 stages
#define STAGE_BYTES 20480
#define GEMM_SMEM (3 * STAGE_BYTES)

template <int MODE>
__global__ __launch_bounds__(256, 2)
void gemm_mma() {
    constexpr int K  = (MODE == 0) ? C_DIM : H_DIM;
    constexpr int Nn = (MODE == 2) ? Q_DIM : H_DIM;
    constexpr int KB = K / 32;

    extern __shared__ char sm[];
    const uint32_t sb = smem_u32(sm);
    const int tid = threadIdx.x;
    const int wid = tid >> 5, lane = tid & 31;
    const int g = lane >> 2, tg = lane & 3;
    const int wm = wid & 3, wn = wid >> 2;
    const int m0 = blockIdx.y * 128, n0 = blockIdx.x * 128;

    const __half* AG = (MODE == 0) ? g_a0 : (MODE == 1 ? g_h1 : g_h2);
    const __half* BG = (MODE == 0) ? g_W1 : (MODE == 1 ? g_W2 : g_W3);

    // A staging: thread -> row arow, 2 chunks of 16B (aq)
    const int arow = tid >> 1;
    const int aq   = (tid & 1) * 2;
    const __half* aP = AG + (size_t)(m0 + arow) * K + aq * 8;
    // B staging: thread -> rows brow, brow+64; 16B chunk bq of 4
    const int brow = tid >> 2;
    const int bq   = tid & 3;
    const __half* bP = BG + (size_t)(n0 + brow) * K + bq * 8;

    auto issueAll = [&](int kb, int b) {
        uint32_t ab = sb + b * STAGE_BYTES + arow * 80 + aq * 16;
        const __half* sh = aP + kb * 32;
        CPA16(ab,      sh);
        CPA16(ab + 16, sh + 8);
        uint32_t bb = sb + b * STAGE_BYTES + 10240 + brow * 80 + bq * 16;
        const __half* bs = bP + kb * 32;
        CPA16(bb,           bs);
        CPA16(bb + 64 * 80, bs + (size_t)64 * K);
    };

    float acc[2][8][4];
#pragma unroll
    for (int mt = 0; mt < 2; ++mt)
#pragma unroll
        for (int nt = 0; nt < 8; ++nt)
#pragma unroll
            for (int j = 0; j < 4; ++j) acc[mt][nt][j] = 0.f;

    // ldmatrix lane-address components
    const int aRowL = lane & 15;
    const int aKhL  = lane >> 4;
    const int bRowL = (lane & 7) + ((lane >> 4) << 3);
    const int bKbL  = (lane >> 3) & 1;

    auto compute = [&](int b) {
        const uint32_t baseA = sb + b * STAGE_BYTES;
        const uint32_t baseB = baseA + 10240;
#pragma unroll
        for (int ck = 0; ck < 2; ++ck) {
            const int k0 = ck * 16;
            const uint32_t aoff = (uint32_t)(aRowL * 80 + (k0 + aKhL * 8) * 2);
            const uint32_t boff = (uint32_t)(bRowL * 80 + (k0 + bKbL * 8) * 2);
            uint32_t ah[2][4];
#pragma unroll
            for (int mt = 0; mt < 2; ++mt) {
                uint32_t ro = (uint32_t)((wm * 32 + mt * 16) * 80);
                ldsm4(ah[mt], baseA + ro + aoff);
            }
#pragma unroll
            for (int p = 0; p < 4; ++p) {
                uint32_t co = (uint32_t)((wn * 64 + p * 16) * 80);
                uint32_t bh4[4];
                ldsm4(bh4, baseB + co + boff);
                const int n0t = p * 2, n1t = p * 2 + 1;
                mma16(acc[0][n0t], ah[0], bh4[0], bh4[1]);
                mma16(acc[1][n0t], ah[1], bh4[0], bh4[1]);
                mma16(acc[0][n1t], ah[0], bh4[2], bh4[3]);
                mma16(acc[1][n1t], ah[1], bh4[2], bh4[3]);
            }
        }
    };

    // ---- 3-stage pipeline ----
    issueAll(0, 0); CPA_COMMIT();
    issueAll(1, 1); CPA_COMMIT();
    CPA_WAIT1();                 // stage 0 landed
    __syncthreads();
    for (int kt = 0; kt < KB; ++kt) {
        compute(kt % 3);
        if (kt + 1 < KB) {
            if (kt + 2 < KB) {
                issueAll(kt + 2, (kt + 2) % 3);
                CPA_COMMIT();
                CPA_WAIT1();     // stage kt+1 landed
            } else {
                CPA_WAIT0();
            }
            __syncthreads();
        }
    }

    // ---- epilogue ----
#pragma unroll
    for (int mt = 0; mt < 2; ++mt) {
        int r = m0 + wm * 32 + mt * 16 + g;
#pragma unroll
        for (int nt = 0; nt < 8; ++nt) {
            int c = n0 + wn * 64 + nt * 8 + tg * 2;
            float* a4 = acc[mt][nt];
            if (MODE == 2) {
                float2 v0 = make_float2(gelu_f(a4[0]), gelu_f(a4[1]));
                float2 v1 = make_float2(gelu_f(a4[2]), gelu_f(a4[3]));
                *(float2*)(g_h3 + (size_t)r * Nn + c)       = v0;
                *(float2*)(g_h3 + (size_t)(r + 8) * Nn + c) = v1;
            } else {
                float b0 = 0.f, b1 = 0.f;
                if (MODE == 1) { b0 = g_bias2[c]; b1 = g_bias2[c + 1]; }
                float f0 = gelu_f(a4[0] + b0), f1 = gelu_f(a4[1] + b1);
                float f2 = gelu_f(a4[2] + b0), f3 = gelu_f(a4[3] + b1);
                __half* Dh = (MODE == 0) ? g_h1 : g_h2;
                *(uint32_t*)(Dh + (size_t)r * Nn + c)       = pack2f(f0, f1);
                *(uint32_t*)(Dh + (size_t)(r + 8) * Nn + c) = pack2f(f2, f3);
            }
        }
    }
}

// ----------------- final: logit, flag-or-write -----------------------------
__global__ __launch_bounds__(256)
void final_kernel(const float* __restrict__ x, const float* __restrict__ prevm,
                  const float* __restrict__ w3, float* __restrict__ out,
                  int write_extra) {
    int row = (blockIdx.x * 256 + threadIdx.x) >> 5;
    int lane = threadIdx.x & 31;
    const float* h3 = g_h3 + (size_t)row * Q_DIM;
    float s = 0.f;
#pragma unroll
    for (int i = 0; i < 8; ++i) s += h3[lane + 32 * i] * w3[lane + 32 * i];
#pragma unroll
    for (int o = 16; o; o >>= 1) s += __shfl_xor_sync(0xffffffffu, s, o);

    float prob = 1.0f / (1.0f + expf(-s));
    float xm = prob * prevm[row];

    if (fabsf(xm - 0.5f) < 1e-3f) {
        if (lane == 0) {
            int idx = atomicAdd(&g_fix_count, 1);
            if (idx < M_TOK) g_fix_list[idx] = row;
        }
        return;
    }
    float m = (xm > 0.5f) ? 1.0f : 0.0f;
    if (lane == 0 && write_extra) {
        out[(size_t)M_TOK * C_DIM + row] = m;
        out[(size_t)M_TOK * C_DIM + M_TOK + row] = (m > 0.f) ? 1.0f : 1e-10f;
    }
    const float4* xr = (const float4*)(x + (size_t)row * C_DIM);
    float4* orow = (float4*)(out + (size_t)row * C_DIM);
#pragma unroll
    for (int i = 0; i < 8; ++i) {
        float4 v = xr[lane + 32 * i];
        v.x *= m; v.y *= m; v.z *= m; v.w *= m;
        orow[lane + 32 * i] = v;
    }
}

// ----------------- batched fixup: exact fp32, 16 rows per block -------------
#define FIX_ROWS 16
#define FIX_SMEM ((FIX_ROWS * 1024 + FIX_ROWS * 512 + 16) * 4)

__global__ __launch_bounds__(256)
void fixup_kernel(const float* __restrict__ x, const float* __restrict__ prevm,
                  const float* __restrict__ WL, const float* __restrict__ Wl1,
                  const float* __restrict__ Wl2, const float* __restrict__ w3,
                  const float* __restrict__ lns, const float* __restrict__ lnb,
                  float* __restrict__ out, int write_extra) {
    extern __shared__ float fs[];
    float* sA  = fs;                                   // [16][1024]
    float* sH  = fs + FIX_ROWS * 1024;                 // [16][512]
    float* sMk = fs + FIX_ROWS * 1024 + FIX_ROWS * 512;
    int cnt = g_fix_count;
    if (cnt > M_TOK) cnt = M_TOK;
    int t = threadIdx.x;

    for (int base = blockIdx.x * FIX_ROWS; base < cnt; base += gridDim.x * FIX_ROWS) {
        int nr = min(FIX_ROWS, cnt - base);
        for (int r = 0; r < nr; ++r) {
            int row = g_fix_list[base + r];
            float mu = g_mu[row], rs = g_rstd[row];
            for (int j = t; j < C_DIM; j += 256)
                sA[r * C_DIM + j] = (x[(size_t)row * C_DIM + j] - mu) * rs * lns[j] + lnb[j];
        }
        __syncthreads();

        float a0[FIX_ROWS], a1[FIX_ROWS];
#pragma unroll
        for (int r = 0; r < FIX_ROWS; ++r) { a0[r] = 0.f; a1[r] = 0.f; }
        for (int k = 0; k < C_DIM; ++k) {
            float w0 = WL[(size_t)k * H_DIM + t];
            float w1 = WL[(size_t)k * H_DIM + t + 256];
#pragma unroll
            for (int r = 0; r < FIX_ROWS; ++r) {
                float av = sA[r * C_DIM + k];
                a0[r] = fmaf(av, w0, a0[r]);
                a1[r] = fmaf(av, w1, a1[r]);
            }
        }
        __syncthreads();
        for (int r = 0; r < nr; ++r) {
            sH[r * H_DIM + t]       = gelu_f(a0[r]);
            sH[r * H_DIM + t + 256] = gelu_f(a1[r]);
        }
        __syncthreads();

        {
            float b0 = g_bias2[t], b1 = g_bias2[t + 256];
#pragma unroll
            for (int r = 0; r < FIX_ROWS; ++r) { a0[r] = b0; a1[r] = b1; }
        }
        for (int k = 0; k < H_DIM; ++k) {
            float w0 = Wl1[(size_t)k * H_DIM + t];
            float w1 = Wl1[(size_t)k * H_DIM + t + 256];
#pragma unroll
            for (int r = 0; r < FIX_ROWS; ++r) {
                float hv = sH[r * H_DIM + k];
                a0[r] = fmaf(hv, w0, a0[r]);
                a1[r] = fmaf(hv, w1, a1[r]);
            }
        }
        __syncthreads();
        for (int r = 0; r < nr; ++r) {
            sA[r * C_DIM + t]       = gelu_f(a0[r]);
            sA[r * C_DIM + t + 256] = gelu_f(a1[r]);
        }
        __syncthreads();

#pragma unroll
        for (int r = 0; r < FIX_ROWS; ++r) a0[r] = 0.f;
        for (int k = 0; k < H_DIM; ++k) {
            float w0 = Wl2[(size_t)k * Q_DIM + t];
#pragma unroll
            for (int r = 0; r < FIX_ROWS; ++r)
                a0[r] = fmaf(sA[r * C_DIM + k], w0, a0[r]);
        }
        __syncthreads();
        for (int r = 0; r < nr; ++r)
            sH[r * H_DIM + t] = gelu_f(a0[r]);
        __syncthreads();

        int w = t >> 5, l = t & 31;
        for (int rr = w; rr < nr; rr += 8) {
            float s = 0.f;
#pragma unroll
            for (int i = 0; i < 8; ++i)
                s += sH[rr * H_DIM + l + 32 * i] * w3[l + 32 * i];
#pragma unroll
            for (int o = 16; o; o >>= 1) s += __shfl_xor_sync(0xffffffffu, s, o);
            if (l == 0) {
                float prob = 1.0f / (1.0f + expf(-s));
                int row = g_fix_list[base + rr];
                float m = (prob * prevm[row] > 0.5f) ? 1.0f : 0.0f;
                sMk[rr] = m;
                if (write_extra) {
                    out[(size_t)M_TOK * C_DIM + row] = m;
                    out[(size_t)M_TOK * C_DIM + M_TOK + row] = (m > 0.f) ? 1.0f : 1e-10f;
                }
            }
        }
        __syncthreads();

        for (int r = 0; r < nr; ++r) {
            int row = g_fix_list[base + r];
            float m = sMk[r];
            const float4* xr = (const float4*)(x + (size_t)row * C_DIM);
            float4* orow = (float4*)(out + (size_t)row * C_DIM);
            float4 v = xr[t];
            v.x *= m; v.y *= m; v.z *= m; v.w *= m;
            orow[t] = v;
        }
        __syncthreads();
    }
}

// ----------------- launch ---------------------------------------------------
extern "C" void kernel_launch(void* const* d_in, const int* in_sizes, int n_in,
                              void* d_out, int out_size) {
    const float* x   = (const float*)d_in[0];
    const float* nf  = (const float*)d_in[1];
    const float* pm  = (const float*)d_in[2];
    const float* lns = (const float*)d_in[3];
    const float* lnb = (const float*)d_in[4];
    const float* WL  = (const float*)d_in[5];
    const float* Wl1 = (const float*)d_in[6];
    const float* Wl2 = (const float*)d_in[7];
    const float* W3  = (const float*)d_in[8];
    float* out = (float*)d_out;

    cudaFuncSetAttribute(gemm_mma<0>, cudaFuncAttributeMaxDynamicSharedMemorySize, GEMM_SMEM);
    cudaFuncSetAttribute(gemm_mma<1>, cudaFuncAttributeMaxDynamicSharedMemorySize, GEMM_SMEM);
    cudaFuncSetAttribute(gemm_mma<2>, cudaFuncAttributeMaxDynamicSharedMemorySize, GEMM_SMEM);
    cudaFuncSetAttribute(fixup_kernel, cudaFuncAttributeMaxDynamicSharedMemorySize, FIX_SMEM);

    ln_apply_kernel<<<M_TOK / 8, 256>>>(x, lns, lnb);
    prep_w_kernel<<<(H_DIM * C_DIM + H_DIM * H_DIM + Q_DIM * H_DIM + 255) / 256, 256>>>(WL, Wl1, Wl2);
    bias2_kernel<<<2, 256>>>(nf, Wl1);

    gemm_mma<0><<<dim3(H_DIM / 128, M_TOK / 128), 256, GEMM_SMEM>>>();
    gemm_mma<1><<<dim3(H_DIM / 128, M_TOK / 128), 256, GEMM_SMEM>>>();
    gemm_mma<2><<<dim3(Q_DIM / 128, M_TOK / 128), 256, GEMM_SMEM>>>();

    int extra = (out_size >= M_TOK * C_DIM + 2 * M_TOK) ? 1 : 0;
    final_kernel<<<M_TOK / 8, 256>>>(x, pm, W3, out, extra);
    fixup_kernel<<<512, 256, FIX_SMEM>>>(x, pm, WL, Wl1, Wl2, W3, lns, lnb, out, extra);
}

// round 17
// speedup vs baseline: 1.2661x; 1.2661x over previous
#include <cuda_runtime.h>
#include <cuda_fp16.h>
#include <cstdint>

#define M_TOK 65536   // B*N
#define C_DIM 1024
#define H_DIM 512
#define Q_DIM 256

// ----------------- device-global scratch ----------------------------------
__device__ float g_mu[M_TOK];
__device__ float g_rstd[M_TOK];
__device__ float g_bias2[H_DIM];
// LN'd input + intermediates, plain fp16, [m][k]
__device__ __half g_a0[(size_t)M_TOK * C_DIM];
__device__ __half g_h1[(size_t)M_TOK * H_DIM];
__device__ __half g_h2[(size_t)M_TOK * H_DIM];
__device__ float  g_h3[(size_t)M_TOK * Q_DIM];
// fp16 weights (single rounding), TRANSPOSED [n][k]
__device__ __half g_W1[H_DIM * C_DIM];
__device__ __half g_W2[H_DIM * H_DIM];
__device__ __half g_W3[Q_DIM * H_DIM];
__device__ int   g_fix_count;
__device__ int   g_fix_list[M_TOK];

// ----------------- helpers ------------------------------------------------
__device__ __forceinline__ float gelu_f(float v) {
    return 0.5f * v * (1.0f + erff(v * 0.70710678118654752440f));
}
__device__ __forceinline__ uint32_t pack2f(float a, float b) {
    __half2 h2 = __halves2half2(__float2half_rn(a), __float2half_rn(b));
    return *reinterpret_cast<uint32_t*>(&h2);
}
typedef unsigned long long ull;
__device__ __forceinline__ void ffma2(ull& d, ull a, ull b) {
    // packed 2-lane fp32 FMA; per-lane RN identical to scalar fmaf
    asm("fma.rn.f32x2 %0, %1, %2, %0;" : "+l"(d) : "l"(a), "l"(b));
}
__device__ __forceinline__ ull dup2(float w) {
    ull r; asm("mov.b64 %0, {%1, %1};" : "=l"(r) : "f"(w)); return r;
}
__device__ __forceinline__ void unpk2(ull v, float& lo, float& hi) {
    asm("mov.b64 {%0, %1}, %2;" : "=f"(lo), "=f"(hi) : "l"(v));
}
#define CPA16(dst, src) \
    asm volatile("cp.async.cg.shared.global [%0], [%1], 16;" :: "r"(dst), "l"(src) : "memory")
#define CPA_COMMIT() asm volatile("cp.async.commit_group;" ::: "memory")
#define CPA_WAIT0()  asm volatile("cp.async.wait_group 0;" ::: "memory")
#define CPA_WAIT1()  asm volatile("cp.async.wait_group 1;" ::: "memory")
__device__ __forceinline__ uint32_t smem_u32(const void* p) {
    uint32_t a;
    asm("{ .reg .u64 t; cvta.to.shared.u64 t, %1; cvt.u32.u64 %0, t; }" : "=r"(a) : "l"(p));
    return a;
}
__device__ __forceinline__ void ldsm4(uint32_t* r, uint32_t addr) {
    asm volatile("ldmatrix.sync.aligned.m8n8.x4.shared.b16 {%0,%1,%2,%3}, [%4];"
                 : "=r"(r[0]), "=r"(r[1]), "=r"(r[2]), "=r"(r[3]) : "r"(addr));
}
__device__ __forceinline__ void mma16(float* d, const uint32_t* a, uint32_t b0, uint32_t b1) {
    asm volatile(
        "mma.sync.aligned.m16n8k16.row.col.f32.f16.f16.f32 "
        "{%0,%1,%2,%3}, {%4,%5,%6,%7}, {%8,%9}, {%0,%1,%2,%3};"
        : "+f"(d[0]), "+f"(d[1]), "+f"(d[2]), "+f"(d[3])
        : "r"(a[0]), "r"(a[1]), "r"(a[2]), "r"(a[3]), "r"(b0), "r"(b1));
}

// ----------------- fused LN stats + apply + fp16 round ---------------------
__global__ __launch_bounds__(256)
void ln_apply_kernel(const float* __restrict__ x,
                     const float* __restrict__ lns, const float* __restrict__ lnb) {
    int row = (blockIdx.x * 256 + threadIdx.x) >> 5;
    int lane = threadIdx.x & 31;
    const float4* xr = (const float4*)(x + (size_t)row * C_DIM);
    float4 v[8];
    float s = 0.f, ss = 0.f;
#pragma unroll
    for (int i = 0; i < 8; ++i) {
        v[i] = xr[lane + 32 * i];
        s  += v[i].x + v[i].y + v[i].z + v[i].w;
        ss += v[i].x * v[i].x + v[i].y * v[i].y + v[i].z * v[i].z + v[i].w * v[i].w;
    }
#pragma unroll
    for (int o = 16; o; o >>= 1) {
        s  += __shfl_xor_sync(0xffffffffu, s, o);
        ss += __shfl_xor_sync(0xffffffffu, ss, o);
    }
    float mu = s * (1.0f / C_DIM);
    float var = ss * (1.0f / C_DIM) - mu * mu;
    float rs = rsqrtf(var + 1e-5f);
    if (lane == 0) { g_mu[row] = mu; g_rstd[row] = rs; }

    __half* dh = g_a0 + (size_t)row * C_DIM;
#pragma unroll
    for (int i = 0; i < 8; ++i) {
        int k = (lane + 32 * i) * 4;
        float4 sc = *(const float4*)(lns + k);
        float4 bi = *(const float4*)(lnb + k);
        float f0 = (v[i].x - mu) * rs * sc.x + bi.x;
        float f1 = (v[i].y - mu) * rs * sc.y + bi.y;
        float f2 = (v[i].z - mu) * rs * sc.z + bi.z;
        float f3 = (v[i].w - mu) * rs * sc.w + bi.w;
        *(uint2*)(dh + k) = make_uint2(pack2f(f0, f1), pack2f(f2, f3));
    }
}

// ----------------- weight prep: transpose + fp16 round ----------------------
__global__ void prep_w_kernel(const float* __restrict__ WL,
                              const float* __restrict__ Wl1,
                              const float* __restrict__ Wl2) {
    int i = blockIdx.x * blockDim.x + threadIdx.x;
    if (i == 0) g_fix_count = 0;
    const int S1 = H_DIM * C_DIM;
    const int S2 = S1 + H_DIM * H_DIM;
    const int S3 = S2 + Q_DIM * H_DIM;
    if (i < S1) {
        int n = i / C_DIM, k = i % C_DIM;
        g_W1[i] = __float2half_rn(WL[(size_t)k * H_DIM + n]);
    } else if (i < S2) {
        int j = i - S1;
        int n = j / H_DIM, k = j % H_DIM;          // Wl1 top half: rows 0..511
        g_W2[j] = __float2half_rn(Wl1[(size_t)k * H_DIM + n]);
    } else if (i < S3) {
        int j = i - S2;
        int n = j / H_DIM, k = j % H_DIM;
        g_W3[j] = __float2half_rn(Wl2[(size_t)k * Q_DIM + n]);
    }
}

// ----------------- bias2 = noise_feature @ W_l1[512:,:] (exact fp32) -------
__global__ void bias2_kernel(const float* __restrict__ nf,
                             const float* __restrict__ Wl1) {
    int j = blockIdx.x * blockDim.x + threadIdx.x;
    const float* wp = Wl1 + (size_t)H_DIM * H_DIM + j;
    float s = 0.f;
    for (int k = 0; k < H_DIM; ++k)
        s += nf[k] * wp[(size_t)k * H_DIM];
    g_bias2[j] = s;
}

// ----------------- fp16 GEMM, 3-stage cp.async pipeline --------------------
// per stage: A 128x80B (10240) | B 128x80B (10240) = 20480; 3 stages
#define STAGE_BYTES 20480
#define GEMM_SMEM (3 * STAGE_BYTES)

template <int MODE>
__global__ __launch_bounds__(256, 2)
void gemm_mma() {
    constexpr int K  = (MODE == 0) ? C_DIM : H_DIM;
    constexpr int Nn = (MODE == 2) ? Q_DIM : H_DIM;
    constexpr int KB = K / 32;

    extern __shared__ char sm[];
    const uint32_t sb = smem_u32(sm);
    const int tid = threadIdx.x;
    const int wid = tid >> 5, lane = tid & 31;
    const int g = lane >> 2, tg = lane & 3;
    const int wm = wid & 3, wn = wid >> 2;
    const int m0 = blockIdx.y * 128, n0 = blockIdx.x * 128;

    const __half* AG = (MODE == 0) ? g_a0 : (MODE == 1 ? g_h1 : g_h2);
    const __half* BG = (MODE == 0) ? g_W1 : (MODE == 1 ? g_W2 : g_W3);

    const int arow = tid >> 1;
    const int aq   = (tid & 1) * 2;
    const __half* aP = AG + (size_t)(m0 + arow) * K + aq * 8;
    const int brow = tid >> 2;
    const int bq   = tid & 3;
    const __half* bP = BG + (size_t)(n0 + brow) * K + bq * 8;

    auto issueAll = [&](int kb, int b) {
        uint32_t ab = sb + b * STAGE_BYTES + arow * 80 + aq * 16;
        const __half* sh = aP + kb * 32;
        CPA16(ab,      sh);
        CPA16(ab + 16, sh + 8);
        uint32_t bb = sb + b * STAGE_BYTES + 10240 + brow * 80 + bq * 16;
        const __half* bs = bP + kb * 32;
        CPA16(bb,           bs);
        CPA16(bb + 64 * 80, bs + (size_t)64 * K);
    };

    float acc[2][8][4];
#pragma unroll
    for (int mt = 0; mt < 2; ++mt)
#pragma unroll
        for (int nt = 0; nt < 8; ++nt)
#pragma unroll
            for (int j = 0; j < 4; ++j) acc[mt][nt][j] = 0.f;

    const int aRowL = lane & 15;
    const int aKhL  = lane >> 4;
    const int bRowL = (lane & 7) + ((lane >> 4) << 3);
    const int bKbL  = (lane >> 3) & 1;

    auto compute = [&](int b) {
        const uint32_t baseA = sb + b * STAGE_BYTES;
        const uint32_t baseB = baseA + 10240;
#pragma unroll
        for (int ck = 0; ck < 2; ++ck) {
            const int k0 = ck * 16;
            const uint32_t aoff = (uint32_t)(aRowL * 80 + (k0 + aKhL * 8) * 2);
            const uint32_t boff = (uint32_t)(bRowL * 80 + (k0 + bKbL * 8) * 2);
            uint32_t ah[2][4];
#pragma unroll
            for (int mt = 0; mt < 2; ++mt) {
                uint32_t ro = (uint32_t)((wm * 32 + mt * 16) * 80);
                ldsm4(ah[mt], baseA + ro + aoff);
            }
#pragma unroll
            for (int p = 0; p < 4; ++p) {
                uint32_t co = (uint32_t)((wn * 64 + p * 16) * 80);
                uint32_t bh4[4];
                ldsm4(bh4, baseB + co + boff);
                const int n0t = p * 2, n1t = p * 2 + 1;
                mma16(acc[0][n0t], ah[0], bh4[0], bh4[1]);
                mma16(acc[1][n0t], ah[1], bh4[0], bh4[1]);
                mma16(acc[0][n1t], ah[0], bh4[2], bh4[3]);
                mma16(acc[1][n1t], ah[1], bh4[2], bh4[3]);
            }
        }
    };

    issueAll(0, 0); CPA_COMMIT();
    issueAll(1, 1); CPA_COMMIT();
    CPA_WAIT1();
    __syncthreads();
    for (int kt = 0; kt < KB; ++kt) {
        compute(kt % 3);
        if (kt + 1 < KB) {
            if (kt + 2 < KB) {
                issueAll(kt + 2, (kt + 2) % 3);
                CPA_COMMIT();
                CPA_WAIT1();
            } else {
                CPA_WAIT0();
            }
            __syncthreads();
        }
    }

#pragma unroll
    for (int mt = 0; mt < 2; ++mt) {
        int r = m0 + wm * 32 + mt * 16 + g;
#pragma unroll
        for (int nt = 0; nt < 8; ++nt) {
            int c = n0 + wn * 64 + nt * 8 + tg * 2;
            float* a4 = acc[mt][nt];
            if (MODE == 2) {
                float2 v0 = make_float2(gelu_f(a4[0]), gelu_f(a4[1]));
                float2 v1 = make_float2(gelu_f(a4[2]), gelu_f(a4[3]));
                *(float2*)(g_h3 + (size_t)r * Nn + c)       = v0;
                *(float2*)(g_h3 + (size_t)(r + 8) * Nn + c) = v1;
            } else {
                float b0 = 0.f, b1 = 0.f;
                if (MODE == 1) { b0 = g_bias2[c]; b1 = g_bias2[c + 1]; }
                float f0 = gelu_f(a4[0] + b0), f1 = gelu_f(a4[1] + b1);
                float f2 = gelu_f(a4[2] + b0), f3 = gelu_f(a4[3] + b1);
                __half* Dh = (MODE == 0) ? g_h1 : g_h2;
                *(uint32_t*)(Dh + (size_t)r * Nn + c)       = pack2f(f0, f1);
                *(uint32_t*)(Dh + (size_t)(r + 8) * Nn + c) = pack2f(f2, f3);
            }
        }
    }
}

// ----------------- final: logit, flag-or-write -----------------------------
__global__ __launch_bounds__(256)
void final_kernel(const float* __restrict__ x, const float* __restrict__ prevm,
                  const float* __restrict__ w3, float* __restrict__ out,
                  int write_extra) {
    int row = (blockIdx.x * 256 + threadIdx.x) >> 5;
    int lane = threadIdx.x & 31;
    const float* h3 = g_h3 + (size_t)row * Q_DIM;
    float s = 0.f;
#pragma unroll
    for (int i = 0; i < 8; ++i) s += h3[lane + 32 * i] * w3[lane + 32 * i];
#pragma unroll
    for (int o = 16; o; o >>= 1) s += __shfl_xor_sync(0xffffffffu, s, o);

    float prob = 1.0f / (1.0f + expf(-s));
    float xm = prob * prevm[row];

    if (fabsf(xm - 0.5f) < 1e-3f) {
        if (lane == 0) {
            int idx = atomicAdd(&g_fix_count, 1);
            if (idx < M_TOK) g_fix_list[idx] = row;
        }
        return;
    }
    float m = (xm > 0.5f) ? 1.0f : 0.0f;
    if (lane == 0 && write_extra) {
        out[(size_t)M_TOK * C_DIM + row] = m;
        out[(size_t)M_TOK * C_DIM + M_TOK + row] = (m > 0.f) ? 1.0f : 1e-10f;
    }
    const float4* xr = (const float4*)(x + (size_t)row * C_DIM);
    float4* orow = (float4*)(out + (size_t)row * C_DIM);
#pragma unroll
    for (int i = 0; i < 8; ++i) {
        float4 v = xr[lane + 32 * i];
        v.x *= m; v.y *= m; v.z *= m; v.w *= m;
        orow[lane + 32 * i] = v;
    }
}

// ----------------- batched fixup: exact fp32, FFMA2 + transposed smem -------
// layout: sA[k][RP] k<1024 (transposed, row index in last dim, pad RP=18)
//         sH[k][RP] k<512, sMk[16]
#define FIX_ROWS 16
#define RP 18
#define FIX_SMEM ((C_DIM * RP + H_DIM * RP + 16) * 4)   // 110,656 B

__global__ __launch_bounds__(256)
void fixup_kernel(const float* __restrict__ x, const float* __restrict__ prevm,
                  const float* __restrict__ WL, const float* __restrict__ Wl1,
                  const float* __restrict__ Wl2, const float* __restrict__ w3,
                  const float* __restrict__ lns, const float* __restrict__ lnb,
                  float* __restrict__ out, int write_extra) {
    extern __shared__ float fs[];
    float* sA  = fs;                         // [1024][RP]
    float* sH  = fs + C_DIM * RP;            // [512][RP]
    float* sMk = fs + C_DIM * RP + H_DIM * RP;
    int cnt = g_fix_count;
    if (cnt > M_TOK) cnt = M_TOK;
    int t = threadIdx.x;

    for (int base = blockIdx.x * FIX_ROWS; base < cnt; base += gridDim.x * FIX_ROWS) {
        int nr = min(FIX_ROWS, cnt - base);
        // load + LN into transposed sA[k][r]; zero pad rows
        for (int j = t; j < C_DIM; j += 256) {
            float sc = lns[j], bi = lnb[j];
            for (int r = 0; r < FIX_ROWS; ++r) {
                float val = 0.f;
                if (r < nr) {
                    int row = g_fix_list[base + r];
                    val = (x[(size_t)row * C_DIM + j] - g_mu[row]) * g_rstd[row] * sc + bi;
                }
                sA[j * RP + r] = val;
            }
        }
        __syncthreads();

        ull acc0[8], acc1[8];
        // ---- layer1: outputs j = t, t+256 ----
#pragma unroll
        for (int q = 0; q < 8; ++q) { acc0[q] = 0ull; acc1[q] = 0ull; }
        for (int k = 0; k < C_DIM; ++k) {
            ull W0 = dup2(WL[(size_t)k * H_DIM + t]);
            ull W1 = dup2(WL[(size_t)k * H_DIM + t + 256]);
            const ull* av = (const ull*)&sA[k * RP];
#pragma unroll
            for (int q = 0; q < 8; ++q) {
                ull a2 = av[q];
                ffma2(acc0[q], a2, W0);
                ffma2(acc1[q], a2, W1);
            }
        }
        __syncthreads();
#pragma unroll
        for (int q = 0; q < 8; ++q) {
            float lo, hi;
            unpk2(acc0[q], lo, hi);
            sH[t * RP + 2 * q]     = gelu_f(lo);
            sH[t * RP + 2 * q + 1] = gelu_f(hi);
            unpk2(acc1[q], lo, hi);
            sH[(t + 256) * RP + 2 * q]     = gelu_f(lo);
            sH[(t + 256) * RP + 2 * q + 1] = gelu_f(hi);
        }
        __syncthreads();

        // ---- layer2: outputs j = t, t+256 (h2 into sA[j][r]) ----
        {
            ull b0 = dup2(g_bias2[t]), b1 = dup2(g_bias2[t + 256]);
#pragma unroll
            for (int q = 0; q < 8; ++q) { acc0[q] = b0; acc1[q] = b1; }
        }
        for (int k = 0; k < H_DIM; ++k) {
            ull W0 = dup2(Wl1[(size_t)k * H_DIM + t]);
            ull W1 = dup2(Wl1[(size_t)k * H_DIM + t + 256]);
            const ull* av = (const ull*)&sH[k * RP];
#pragma unroll
            for (int q = 0; q < 8; ++q) {
                ull a2 = av[q];
                ffma2(acc0[q], a2, W0);
                ffma2(acc1[q], a2, W1);
            }
        }
        __syncthreads();
#pragma unroll
        for (int q = 0; q < 8; ++q) {
            float lo, hi;
            unpk2(acc0[q], lo, hi);
            sA[t * RP + 2 * q]     = gelu_f(lo);
            sA[t * RP + 2 * q + 1] = gelu_f(hi);
            unpk2(acc1[q], lo, hi);
            sA[(t + 256) * RP + 2 * q]     = gelu_f(lo);
            sA[(t + 256) * RP + 2 * q + 1] = gelu_f(hi);
        }
        __syncthreads();

        // ---- layer3: output j = t (h3 into sH[j][r], j < 256) ----
#pragma unroll
        for (int q = 0; q < 8; ++q) acc0[q] = 0ull;
        for (int k = 0; k < H_DIM; ++k) {
            ull W0 = dup2(Wl2[(size_t)k * Q_DIM + t]);
            const ull* av = (const ull*)&sA[k * RP];
#pragma unroll
            for (int q = 0; q < 8; ++q) ffma2(acc0[q], av[q], W0);
        }
        __syncthreads();
#pragma unroll
        for (int q = 0; q < 8; ++q) {
            float lo, hi;
            unpk2(acc0[q], lo, hi);
            sH[t * RP + 2 * q]     = gelu_f(lo);
            sH[t * RP + 2 * q + 1] = gelu_f(hi);
        }
        __syncthreads();

        // ---- logit + mask: warp w handles rows w, w+8 ----
        int w = t >> 5, l = t & 31;
        for (int rr = w; rr < nr; rr += 8) {
            float s = 0.f;
#pragma unroll
            for (int i = 0; i < 8; ++i)
                s += sH[(l + 32 * i) * RP + rr] * w3[l + 32 * i];
#pragma unroll
            for (int o = 16; o; o >>= 1) s += __shfl_xor_sync(0xffffffffu, s, o);
            if (l == 0) {
                float prob = 1.0f / (1.0f + expf(-s));
                int row = g_fix_list[base + rr];
                float m = (prob * prevm[row] > 0.5f) ? 1.0f : 0.0f;
                sMk[rr] = m;
                if (write_extra) {
                    out[(size_t)M_TOK * C_DIM + row] = m;
                    out[(size_t)M_TOK * C_DIM + M_TOK + row] = (m > 0.f) ? 1.0f : 1e-10f;
                }
            }
        }
        __syncthreads();

        // ---- gated output rows ----
        for (int r = 0; r < nr; ++r) {
            int row = g_fix_list[base + r];
            float m = sMk[r];
            const float4* xr = (const float4*)(x + (size_t)row * C_DIM);
            float4* orow = (float4*)(out + (size_t)row * C_DIM);
            float4 v = xr[t];
            v.x *= m; v.y *= m; v.z *= m; v.w *= m;
            orow[t] = v;
        }
        __syncthreads();
    }
}

// ----------------- launch ---------------------------------------------------
extern "C" void kernel_launch(void* const* d_in, const int* in_sizes, int n_in,
                              void* d_out, int out_size) {
    const float* x   = (const float*)d_in[0];
    const float* nf  = (const float*)d_in[1];
    const float* pm  = (const float*)d_in[2];
    const float* lns = (const float*)d_in[3];
    const float* lnb = (const float*)d_in[4];
    const float* WL  = (const float*)d_in[5];
    const float* Wl1 = (const float*)d_in[6];
    const float* Wl2 = (const float*)d_in[7];
    const float* W3  = (const float*)d_in[8];
    float* out = (float*)d_out;

    cudaFuncSetAttribute(gemm_mma<0>, cudaFuncAttributeMaxDynamicSharedMemorySize, GEMM_SMEM);
    cudaFuncSetAttribute(gemm_mma<1>, cudaFuncAttributeMaxDynamicSharedMemorySize, GEMM_SMEM);
    cudaFuncSetAttribute(gemm_mma<2>, cudaFuncAttributeMaxDynamicSharedMemorySize, GEMM_SMEM);
    cudaFuncSetAttribute(fixup_kernel, cudaFuncAttributeMaxDynamicSharedMemorySize, FIX_SMEM);

    ln_apply_kernel<<<M_TOK / 8, 256>>>(x, lns, lnb);
    prep_w_kernel<<<(H_DIM * C_DIM + H_DIM * H_DIM + Q_DIM * H_DIM + 255) / 256, 256>>>(WL, Wl1, Wl2);
    bias2_kernel<<<2, 256>>>(nf, Wl1);

    gemm_mma<0><<<dim3(H_DIM / 128, M_TOK / 128), 256, GEMM_SMEM>>>();
    gemm_mma<1><<<dim3(H_DIM / 128, M_TOK / 128), 256, GEMM_SMEM>>>();
    gemm_mma<2><<<dim3(Q_DIM / 128, M_TOK / 128), 256, GEMM_SMEM>>>();

    int extra = (out_size >= M_TOK * C_DIM + 2 * M_TOK) ? 1 : 0;
    final_kernel<<<M_TOK / 8, 256>>>(x, pm, W3, out, extra);
    fixup_kernel<<<512, 256, FIX_SMEM>>>(x, pm, WL, Wl1, Wl2, W3, lns, lnb, out, extra);
}